// round 3
// baseline (speedup 1.0000x reference)
#include <cuda_runtime.h>

// MedianFilter: xs [B=4,T=32,N=128,D=32] f32, A [1,128,128] i32.
// Per (b,t,n,d): lower median over {prev-self (t>0), next-self (t<T-1),
//   xs[b,t,j,d] for j with (A+I)[n][j]!=0}.
// Three uniform scans: 4-bit hist @28, filtered 4-bit hist @24 (exact 8-bit
// prefix), collection of 8-bit-prefix matches into a tiny shared buffer,
// then register-sized nibble radix over <=~3 survivors. Exact.

#define Bc 4
#define Tc 32
#define Nc 128
#define Dc 32
#define NT 256          // threads per block
#define NODES_PB 32     // nodes per block (quarter of N)
#define SLOTS 16

__device__ __forceinline__ unsigned f2u(float f) {
    unsigned s = __float_as_uint(f);
    return s ^ ((unsigned)((int)s >> 31) | 0x80000000u);
}
__device__ __forceinline__ float u2f(unsigned u) {
    unsigned s = (u & 0x80000000u) ? (u ^ 0x80000000u) : ~u;
    return __uint_as_float(s);
}

// Select nibble bin containing rank m from byte-packed histograms
// h0 (bins 0-7) / h1 (bins 8-15). Total count <= 130 so bytes don't overflow.
// Updates m to rank within the bin; rem = bin count.
__device__ __forceinline__ int select_bin(unsigned long long h0,
                                          unsigned long long h1,
                                          unsigned &m, unsigned &rem)
{
    unsigned long long s0 = h0 * 0x0101010101010101ull;
    unsigned total0 = (unsigned)(s0 >> 56);
    unsigned long long S, H;
    int base;
    unsigned mm = m;
    if (mm < total0) { S = s0; H = h0; base = 0; }
    else {
        mm -= total0;
        S = h1 * 0x0101010101010101ull; H = h1; base = 8;
    }
    int g = 0;
    if ((unsigned)((S >> 24) & 0xFF) <= mm) g = 4;
    if ((unsigned)((S >> (8 * (g + 1))) & 0xFF) <= mm) g += 2;
    if ((unsigned)((S >> (8 * g)) & 0xFF) <= mm) g += 1;
    unsigned before = g ? (unsigned)((S >> (8 * (g - 1))) & 0xFF) : 0u;
    rem = (unsigned)((H >> (8 * g)) & 0xFF);
    m = mm - before;
    return base + g;
}

// unfiltered hist of nibble at `shift`
#define HIST(u_)                                                    \
    {                                                               \
        unsigned nib_ = ((u_) >> shift) & 15u;                      \
        unsigned long long inc_ = 1ull << ((nib_ & 7u) * 8u);       \
        if (nib_ & 8u) h1 += inc_; else h0 += inc_;                 \
    }

// hist of nibble at `shift`, counting only candidates whose bits above
// shift+4 match `prefix`
#define HISTF(u_)                                                   \
    {                                                               \
        unsigned u__ = (u_);                                        \
        bool match_ = ((u__ ^ prefix) >> (shift + 4)) == 0u;        \
        unsigned nib_ = (u__ >> shift) & 15u;                       \
        unsigned long long inc_ =                                   \
            match_ ? (1ull << ((nib_ & 7u) * 8u)) : 0ull;           \
        if (nib_ & 8u) h1 += inc_; else h0 += inc_;                 \
    }

__global__ __launch_bounds__(NT, 5)
void median_kernel(const float* __restrict__ xs,
                   const int* __restrict__ A,
                   float* __restrict__ out)
{
    __shared__ unsigned tile[Nc * Dc];              // 16KB (whole frame)
    __shared__ unsigned char nbr[NODES_PB * Nc];    // 4KB (this block's rows)
    __shared__ short cnt[NODES_PB];
    __shared__ unsigned buf[SLOTS * NT];            // 16KB survivor buffer

    const int bid  = blockIdx.x;
    const int bt   = bid >> 2;          // 0..127
    const int q    = bid & 3;           // node quarter
    const int t    = bt & (Tc - 1);
    const int tid  = threadIdx.x;
    const int lane = tid & 31;
    const int w    = tid >> 5;          // 0..7
    const int nbase = q * NODES_PB;

    const float* cur = xs + (size_t)bt * (Nc * Dc);
    #pragma unroll
    for (int i = tid; i < Nc * Dc; i += NT) tile[i] = f2u(cur[i]);

    if (tid < NODES_PB) {
        const int* row = A + (nbase + tid) * Nc;
        int c = 0;
        #pragma unroll 4
        for (int j = 0; j < Nc; j++)
            if (row[j] != 0 || j == nbase + tid) nbr[tid * Nc + (c++)] = (unsigned char)j;
        cnt[tid] = (short)c;
    }
    __syncthreads();

    const bool hasPrev = (t > 0);
    const bool hasNext = (t < Tc - 1);
    const float* prevp = xs + (size_t)(bt - 1) * (Nc * Dc);
    const float* nextp = xs + (size_t)(bt + 1) * (Nc * Dc);

    #pragma unroll 1
    for (int it = 0; it < NODES_PB / 8; it++) {
        const int nl = w + 8 * it;                  // local node 0..31
        const int n  = nbase + nl;
        const int k  = cnt[nl];
        const unsigned char* lst = &nbr[nl * Nc];
        const int ktot = k + (int)hasPrev + (int)hasNext;
        unsigned m = (unsigned)((ktot - 1) >> 1);

        const unsigned prevU = hasPrev ? f2u(prevp[n * Dc + lane]) : 0u;
        const unsigned nextU = hasNext ? f2u(nextp[n * Dc + lane]) : 0u;

        // ---- pass 1: nibble @28 (uniform scan) ----
        unsigned g1, rem1;
        {
            const int shift = 28;
            unsigned long long h0 = 0ull, h1 = 0ull;
            for (int i = 0; i < k; i++) {
                unsigned u = tile[(((int)lst[i]) << 5) | lane];
                HIST(u);
            }
            if (hasPrev) HIST(prevU);
            if (hasNext) HIST(nextU);
            g1 = (unsigned)select_bin(h0, h1, m, rem1);
        }

        // ---- pass 2: nibble @24, filtered on top nibble (uniform scan) ----
        unsigned g2, rem2;
        {
            const int shift = 24;
            const unsigned prefix = g1 << 28;
            unsigned long long h0 = 0ull, h1 = 0ull;
            for (int i = 0; i < k; i++) {
                unsigned u = tile[(((int)lst[i]) << 5) | lane];
                HISTF(u);
            }
            if (hasPrev) HISTF(prevU);
            if (hasNext) HISTF(nextU);
            g2 = (unsigned)select_bin(h0, h1, m, rem2);
        }
        const unsigned pref8 = (g1 << 4) | g2;

        // ---- pass 3: collect 8-bit-prefix matches into buffer ----
        int c = 0;
        for (int i = 0; i < k; i++) {
            unsigned u = tile[(((int)lst[i]) << 5) | lane];
            if ((u >> 24) == pref8) {
                if (c < SLOTS) buf[c * NT + tid] = u;
                c++;
            }
        }
        if (hasPrev && (prevU >> 24) == pref8) { if (c < SLOTS) buf[c * NT + tid] = prevU; c++; }
        if (hasNext && (nextU >> 24) == pref8) { if (c < SLOTS) buf[c * NT + tid] = nextU; c++; }

        unsigned result;
        const bool ovf = (c > SLOTS);

        if (__any_sync(0xFFFFFFFFu, ovf)) {
            // ----- rare general fallback: filtered full scans on lower bits -----
            if (ovf) {
                unsigned prefix = pref8 << 24;
                bool done = false;
                #pragma unroll 1
                for (int p = 2; p < 8 && !done; p++) {
                    const int shift = 28 - 4 * p;
                    unsigned long long h0 = 0ull, h1 = 0ull;
                    for (int i = 0; i < k; i++) {
                        unsigned u = tile[(((int)lst[i]) << 5) | lane];
                        HISTF(u);
                    }
                    if (hasPrev) HISTF(prevU);
                    if (hasNext) HISTF(nextU);
                    unsigned rem;
                    int g = select_bin(h0, h1, m, rem);
                    prefix |= (unsigned)g << shift;
                    if (rem == 1u) {
                        unsigned r = prefix;
                        for (int i = 0; i < k; i++) {
                            unsigned u = tile[(((int)lst[i]) << 5) | lane];
                            if (((u ^ prefix) >> shift) == 0u) r = u;
                        }
                        if (hasPrev && ((prevU ^ prefix) >> shift) == 0u) r = prevU;
                        if (hasNext && ((nextU ^ prefix) >> shift) == 0u) r = nextU;
                        result = r;
                        done = true;
                    }
                }
                if (!done) result = prefix;   // survivors identical to prefix
            }
        }

        if (!ovf) {
            if (c == 1) {
                result = buf[tid];
            } else {
                // tiny nibble radix over c (<= SLOTS) buffered survivors
                unsigned prefix = pref8 << 24;
                bool done = false;
                #pragma unroll 1
                for (int p = 2; p < 8; p++) {
                    if (__all_sync(__activemask(), done || c <= 1)) break;
                    const int shift = 28 - 4 * p;
                    if (!done && c > 1) {
                        unsigned long long h0 = 0ull, h1 = 0ull;
                        for (int i = 0; i < c; i++) {
                            unsigned u = buf[i * NT + tid];
                            HIST(u);
                        }
                        unsigned rem;
                        int g = select_bin(h0, h1, m, rem);
                        prefix |= (unsigned)g << shift;
                        int c2 = 0;
                        for (int i = 0; i < c; i++) {
                            unsigned u = buf[i * NT + tid];
                            if (((u >> shift) & 15u) == (unsigned)g) { buf[c2 * NT + tid] = u; c2++; }
                        }
                        c = c2;
                        if (c == 1) { result = buf[tid]; done = true; }
                    }
                }
                if (!done) result = (c == 1) ? buf[tid] : prefix;
            }
        }

        out[(size_t)bt * (Nc * Dc) + n * Dc + lane] = u2f(result);
    }
}

extern "C" void kernel_launch(void* const* d_in, const int* in_sizes, int n_in,
                              void* d_out, int out_size)
{
    const float* xs  = (const float*)d_in[0];
    const int*   A   = (const int*)d_in[1];
    float*       out = (float*)d_out;
    (void)in_sizes; (void)n_in; (void)out_size;

    cudaFuncSetAttribute(median_kernel,
                         cudaFuncAttributePreferredSharedMemoryCarveout, 100);
    median_kernel<<<Bc * Tc * 4, NT>>>(xs, A, out);
}